// round 2
// baseline (speedup 1.0000x reference)
#include <cuda_runtime.h>

#define Bq  256
#define Nn  2048
#define Dd  512
#define Hh  8
#define DHh 64
#define NK  2047   // N-1 keys per row

// mask representation: 0 = int8 (1 byte/bool), 1 = int32, 2 = float32
__device__ int g_mask_mode;

__global__ void detect_mask_mode_kernel(const unsigned int* __restrict__ mw) {
    if (threadIdx.x == 0 && blockIdx.x == 0) {
        int all01 = 1, allf = 1;
        for (int i = 0; i < 4096; ++i) {
            unsigned v = mw[i];
            if (v != 0u && v != 1u) all01 = 0;
            if (v != 0u && v != 0x3F800000u) allf = 0;
        }
        g_mask_mode = all01 ? 1 : (allf ? 2 : 0);
    }
}

__global__ __launch_bounds__(256) void mha_fused_kernel(
    const float* __restrict__ ego,          // (B,1,D)
    const void*  __restrict__ mask,         // (B,N) bool in unknown encoding
    const float* __restrict__ keys,         // (H,B,NK,DH)
    const float* __restrict__ value,        // (B,NK,DH)
    const float* __restrict__ W_q,          // (H,D,DH)
    float* __restrict__ out)                // (B,1,D): out[b][h*64+k]
{
    __shared__ float sc[NK + 1];     // scores, then p
    __shared__ float ego_sm[Dd];
    __shared__ float q_sm[DHh];
    __shared__ float red[256];
    __shared__ float wred[8];
    __shared__ float gmax_sm, ginv_sm;
    __shared__ unsigned char msk[NK + 1];

    const int bid  = blockIdx.x;
    const int b    = bid >> 3;      // b-major: 8 heads of same b adjacent -> value L2 reuse
    const int h    = bid & 7;
    const int t    = threadIdx.x;
    const int w    = t >> 5;
    const int lane = t & 31;

    // ---- stage mask row [b][1..N-1] into smem using detected encoding ----
    {
        const int mode = g_mask_mode;
        if (mode == 0) {
            const unsigned char* m8 = (const unsigned char*)mask + (size_t)b * Nn + 1;
            for (int n = t; n < NK; n += 256) msk[n] = m8[n];
        } else if (mode == 1) {
            const int* m32 = (const int*)mask + (size_t)b * Nn + 1;
            for (int n = t; n < NK; n += 256) msk[n] = (unsigned char)(m32[n] != 0);
        } else {
            const float* mf = (const float*)mask + (size_t)b * Nn + 1;
            for (int n = t; n < NK; n += 256) msk[n] = (unsigned char)(mf[n] != 0.0f);
        }
    }

    // ---- load ego row into smem ----
    for (int i = t; i < Dd; i += 256) ego_sm[i] = ego[b * Dd + i];
    __syncthreads();

    // ---- q[k] = sum_d ego[d] * W_q[h][d][k]  (4 threads per k, 128 d each) ----
    {
        const int k     = t & 63;
        const int dpart = t >> 6;                 // 0..3
        const float* wq = W_q + (size_t)h * Dd * DHh + k;
        float acc = 0.f;
        const int d0 = dpart * 128;
        #pragma unroll 4
        for (int d = d0; d < d0 + 128; ++d)
            acc += ego_sm[d] * wq[(size_t)d * DHh];
        red[t] = acc;
    }
    __syncthreads();
    if (t < DHh)
        q_sm[t] = red[t] + red[t + 64] + red[t + 128] + red[t + 192];
    __syncthreads();

    // ---- Phase 1: scores[n] = (q . keys[n]) / 8, masked ----
    const float* kbase = keys + (size_t)(h * Bq + b) * NK * DHh;

    const int half = lane >> 4;            // 0 or 1
    const int kofs = (lane & 15) * 4;      // 4 floats per lane
    const float4 q4 = *(const float4*)(q_sm + kofs);

    float wmax = -3.0e38f;

    for (int n0 = w * 4; n0 < NK; n0 += 32) {
        const int nA = n0 + half;          // rows n0, n0+1
        const int nB = n0 + 2 + half;      // rows n0+2, n0+3
        float4 a  = make_float4(0.f, 0.f, 0.f, 0.f);
        float4 bb = make_float4(0.f, 0.f, 0.f, 0.f);
        if (nA < NK) a  = *(const float4*)(kbase + (size_t)nA * DHh + kofs);
        if (nB < NK) bb = *(const float4*)(kbase + (size_t)nB * DHh + kofs);

        float sA = a.x * q4.x + a.y * q4.y + a.z * q4.z + a.w * q4.w;
        float sB = bb.x * q4.x + bb.y * q4.y + bb.z * q4.z + bb.w * q4.w;

        #pragma unroll
        for (int o = 8; o; o >>= 1) {
            sA += __shfl_xor_sync(0xffffffffu, sA, o);
            sB += __shfl_xor_sync(0xffffffffu, sB, o);
        }

        if (nA < NK) {
            float s = sA * 0.125f;
            if (!msk[nA]) s = -1.0e30f;
            wmax = fmaxf(wmax, s);
            if ((lane & 15) == 0) sc[nA] = s;
        }
        if (nB < NK) {
            float s = sB * 0.125f;
            if (!msk[nB]) s = -1.0e30f;
            wmax = fmaxf(wmax, s);
            if ((lane & 15) == 0) sc[nB] = s;
        }
    }

    // ---- reduce max across warps ----
    #pragma unroll
    for (int o = 16; o; o >>= 1)
        wmax = fmaxf(wmax, __shfl_xor_sync(0xffffffffu, wmax, o));
    if (lane == 0) wred[w] = wmax;
    __syncthreads();
    if (t == 0) {
        float g = wred[0];
        #pragma unroll
        for (int i = 1; i < 8; ++i) g = fmaxf(g, wred[i]);
        gmax_sm = g;
    }
    __syncthreads();
    const float gmax = gmax_sm;

    // ---- Phase 2: exponentiate in place + sum ----
    float lsum = 0.f;
    for (int n = t; n < NK; n += 256) {
        float e = __expf(sc[n] - gmax);
        sc[n] = e;
        lsum += e;
    }
    #pragma unroll
    for (int o = 16; o; o >>= 1)
        lsum += __shfl_xor_sync(0xffffffffu, lsum, o);
    if (lane == 0) wred[w] = lsum;
    __syncthreads();
    if (t == 0) {
        float s = 0.f;
        #pragma unroll
        for (int i = 0; i < 8; ++i) s += wred[i];
        ginv_sm = 1.0f / s;
    }
    __syncthreads();
    const float inv = ginv_sm;

    // ---- Phase 3: out[k] = inv * sum_n p[n] * value[b][n][k] ----
    {
        const int k  = t & 63;
        const int nq = t >> 6;   // 0..3: n-quarter
        const float* vp = value + (size_t)b * NK * DHh + k;
        float acc = 0.f;
        int n = nq;
        #pragma unroll 4
        for (; n + 12 < NK; n += 16) {
            float p0 = sc[n];      float v0 = vp[(size_t)n * DHh];
            float p1 = sc[n + 4];  float v1 = vp[(size_t)(n + 4) * DHh];
            float p2 = sc[n + 8];  float v2 = vp[(size_t)(n + 8) * DHh];
            float p3 = sc[n + 12]; float v3 = vp[(size_t)(n + 12) * DHh];
            acc += p0 * v0 + p1 * v1 + p2 * v2 + p3 * v3;
        }
        for (; n < NK; n += 4)
            acc += sc[n] * vp[(size_t)n * DHh];
        red[t] = acc;
    }
    __syncthreads();
    if (t < DHh) {
        float r = (red[t] + red[t + 64] + red[t + 128] + red[t + 192]) * inv;
        out[(size_t)b * Dd + h * DHh + t] = r;
    }
}

extern "C" void kernel_launch(void* const* d_in, const int* in_sizes, int n_in,
                              void* d_out, int out_size) {
    // Bind inputs by element count (all five are pairwise distinct) so we do
    // not depend on metadata ordering.
    const float* ego   = nullptr;
    const void*  mask  = nullptr;
    const float* keys  = nullptr;
    const float* value = nullptr;
    const float* W_q   = nullptr;

    for (int i = 0; i < n_in; ++i) {
        switch (in_sizes[i]) {
            case Bq * Dd:                 ego   = (const float*)d_in[i]; break; // 131072
            case Bq * Nn:                 mask  = d_in[i];               break; // 524288
            case Hh * Bq * NK * DHh:      keys  = (const float*)d_in[i]; break; // 268173312
            case Bq * NK * DHh:           value = (const float*)d_in[i]; break; // 33521664
            case Hh * Dd * DHh:           W_q   = (const float*)d_in[i]; break; // 262144
            default: break;
        }
    }

    float* out = (float*)d_out;

    detect_mask_mode_kernel<<<1, 32>>>((const unsigned int*)mask);
    mha_fused_kernel<<<Hh * Bq, 256>>>(ego, mask, keys, value, W_q, out);
}